// round 7
// baseline (speedup 1.0000x reference)
#include <cuda_runtime.h>
#include <cstdint>
#include <cstddef>

#define B_   2
#define P_   8192
#define NNB  24
#define C1_  32
#define C2_  32
#define K_   13
#define A_   12
#define DR_  (C2_*A_)   /* 384 */
#define CA_  (C1_*A_)   /* 384 */
#define BP_  (B_*P_)    /* 16384 */

#define CHUNK 24        /* K cols per stage (= 2 c-planes) */
#define CPK   16        /* chunks per k-segment (384/24) */
#define NKS   3         /* m16n8k8 steps per chunk */
#define TCH   (K_*CPK)  /* 208 chunks */
#define SROW  28        /* smem row stride (floats) = 112B, conflict-free */
#define NSTG  4         /* pipeline stages */
#define NTHR  256

// stage layout: A 128 rows + B 192 rows, each SROW floats
#define STG_A_FL  (128*SROW)            /* 3584 */
#define STG_FL    (STG_A_FL + 192*SROW) /* 8960 */

// ---- scratch (device globals; no allocation allowed) ----
__device__ float WTt_g[K_*DR_*CA_];  // [k][dr][ca], tf32-rounded (~7.7MB)
__device__ float md_g[BP_*3];
__device__ float kpo_g[C2_*K_*3];
__device__ float be_g[C2_*A_];

__device__ __forceinline__ uint32_t f2tf32(float x) {
    uint32_t u;
    asm("cvt.rna.tf32.f32 %0, %1;" : "=r"(u) : "f"(x));
    return u;
}
__device__ __forceinline__ uint32_t smem_u32(const void* p) {
    uint32_t a;
    asm("{ .reg .u64 t; cvta.to.shared.u64 t, %1; cvt.u32.u64 %0, t; }" : "=r"(a) : "l"(p));
    return a;
}
__device__ __forceinline__ void cp16(uint32_t dst, const void* src) {
    asm volatile("cp.async.cg.shared.global [%0], [%1], 16;" :: "r"(dst), "l"(src));
}
#define CP_COMMIT() asm volatile("cp.async.commit_group;" ::: "memory")
#define CP_WAIT2()  asm volatile("cp.async.wait_group 2;" ::: "memory")

__device__ __forceinline__ void mma_tf32(float& c0, float& c1, float& c2, float& c3,
                                         uint32_t a0, uint32_t a1, uint32_t a2, uint32_t a3,
                                         uint32_t b0, uint32_t b1) {
    asm volatile("mma.sync.aligned.m16n8k8.row.col.f32.tf32.tf32.f32 "
                 "{%0,%1,%2,%3}, {%4,%5,%6,%7}, {%8,%9}, {%0,%1,%2,%3};"
                 : "+f"(c0), "+f"(c1), "+f"(c2), "+f"(c3)
                 : "r"(a0), "r"(a1), "r"(a2), "r"(a3), "r"(b0), "r"(b1));
}

// ===================== prep kernels =====================
__global__ void build_wt(const float* __restrict__ W,
                         const float* __restrict__ kpw,
                         const int*   __restrict__ idx_map,
                         const int*   __restrict__ tivr,
                         const int*   __restrict__ tir) {
    int idx = blockIdx.x * blockDim.x + threadIdx.x;
    const int total = K_*DR_*CA_;
    for (; idx < total; idx += gridDim.x * blockDim.x) {
        int ca = idx % CA_;
        int t  = idx / CA_;
        int n  = t % DR_;
        int k  = t / DR_;
        int d = n / A_, r = n % A_;
        int c = ca / A_, a = ca % A_;
        int j = idx_map[tivr[r*K_ + k]*A_ + tir[r*A_ + a]];
        float v = W[(d*C1_ + c)*36 + j] * kpw[d*36 + j];
        ((uint32_t*)WTt_g)[idx] = f2tf32(v);
    }
}

__global__ void mean_dir_k(const int* __restrict__ nbr_idx,
                           const float* __restrict__ verts) {
    int bp = blockIdx.x * blockDim.x + threadIdx.x;
    if (bp >= BP_) return;
    int b = bp >> 13;
    int p = bp & (P_-1);
    const float* vb = verts + b * P_ * 3;
    float vx = vb[p*3+0], vy = vb[p*3+1], vz = vb[p*3+2];
    float sx = 0.f, sy = 0.f, sz = 0.f;
    const int* ni = nbr_idx + bp * NNB;
#pragma unroll 4
    for (int n = 0; n < NNB; n++) {
        int q = ni[n];
        float dx = vb[q*3+0] - vx;
        float dy = vb[q*3+1] - vy;
        float dz = vb[q*3+2] - vz;
        float nrm = sqrtf(dx*dx + dy*dy + dz*dz);
        float s = 1.0f / fmaxf(nrm, 1e-12f);
        sx += dx*s; sy += dy*s; sz += dz*s;
    }
    const float inv = 1.0f / (float)NNB;
    md_g[bp*3+0] = sx * inv;
    md_g[bp*3+1] = sy * inv;
    md_g[bp*3+2] = sz * inv;
}

__global__ void prep_small(const float* __restrict__ kpw,
                           const float* __restrict__ vs,
                           const int*   __restrict__ idx_map,
                           const int*   __restrict__ tivr,
                           const float* __restrict__ bias,
                           const int*   __restrict__ lvl) {
    int t = threadIdx.x;
    if (t < C2_*K_) {
        int d = t / K_, k = t % K_;
        float s0 = 0.f, s1 = 0.f, s2 = 0.f;
        for (int a = 0; a < A_; a++) {
            float w = kpw[d*36 + idx_map[k*A_ + a]];
            s0 += w * vs[a*3+0];
            s1 += w * vs[a*3+1];
            s2 += w * vs[a*3+2];
        }
        float nrm = sqrtf(s0*s0 + s1*s1 + s2*s2);
        float inv = 1.0f / fmaxf(nrm, 1e-12f);
        kpo_g[t*3+0] = s0*inv;
        kpo_g[t*3+1] = s1*inv;
        kpo_g[t*3+2] = s2*inv;
    }
    if (t < C2_*A_) {
        int d = t / A_, r = t % A_;
        float s = 0.f;
        for (int k = 0; k < K_; k++)
            s += bias[d*5 + lvl[tivr[r*K_ + k]]];
        be_g[t] = s;
    }
}

// ===================== main mma.sync tf32 kernel =====================
// 256 threads, warp grid 2m x 4n (warp tile 64x48), CTA tile 128x192.
// 4-stage cp.async ring, 1 syncthreads per chunk, all accumulators in regs.
// smem (floats):
//   STAGES [4][8960] @0      (35840)
//   PW  [128][17]    @35840  (2176)
//   MD  [128][3]     @38016  (384)
//   KPO [16][13][3]  @38400  (624)
//   BE  [192]        @39024  (192)
#define OFF_PW  35840
#define OFF_MD  38016
#define OFF_KPO 38400
#define OFF_BE  39024
#define SMEM_FLOATS 39216
#define SMEM_BYTES (SMEM_FLOATS*4)

__global__ __launch_bounds__(NTHR, 1) void equi_mma(const float* __restrict__ fm,
                                                    float* __restrict__ out) {
    extern __shared__ float s[];
    float* PW  = s + OFF_PW;
    float* MD  = s + OFF_MD;
    float* KPO = s + OFF_KPO;
    float* BE  = s + OFF_BE;
    const uint32_t sS = smem_u32(s);

    const int tid  = threadIdx.x;
    const int wid  = tid >> 5;
    const int lane = tid & 31;
    const int gid  = lane >> 2;
    const int tig  = lane & 3;

    const int Ntile = blockIdx.x;        // 0..1
    const int Mtile = blockIdx.y;        // 0..127
    const int b  = Mtile >> 6;
    const int p0 = (Mtile & 63) << 7;
    const int n0 = Ntile * 192;
    const int d0 = Ntile * 16;

    // warp grid 2(m) x 4(n): warp tile 64m x 48n
    const int m0w = (wid & 1) * 64;
    const int n0w = (wid >> 1) * 48;

    for (int i = tid; i < 128*3; i += NTHR) MD[i]  = md_g[(size_t)Mtile*128*3 + i];
    for (int i = tid; i < 16*K_*3; i += NTHR) KPO[i] = kpo_g[d0*(K_*3) + i];
    if (tid < 192) BE[tid] = be_g[d0*A_ + tid];

    const float* fmb = fm + (size_t)b * C1_ * K_ * P_ * A_;

    float acc_k[4][6][4], acc_o[4][6][4];
#pragma unroll
    for (int mt = 0; mt < 4; mt++)
#pragma unroll
        for (int nt = 0; nt < 6; nt++)
#pragma unroll
            for (int q = 0; q < 4; q++) { acc_k[mt][nt][q] = 0.f; acc_o[mt][nt][q] = 0.f; }

    // A copy mapping: thread -> (row = tid&127, cseg = tid>>7)
    const int rowA = tid & 127;
    const int csA  = tid >> 7;

    auto issue_copies = [&](int t) {
        int k  = t >> 4;
        int j  = t & 15;
        int st = t & 3;
        uint32_t stb = sS + (uint32_t)(st*STG_FL)*4u;
        // A: 128 rows x 24 cols (2 c-planes), 3 x cp16 per thread
        {
            int c = j*2 + csA;
            const float* src = fmb + ((size_t)(c*K_ + k)*P_ + p0 + rowA)*A_;
            uint32_t dst = stb + (uint32_t)(rowA*SROW + csA*12)*4u;
#pragma unroll
            for (int q = 0; q < 3; q++)
                cp16(dst + q*16u, src + q*4);
        }
        // B: 192 rows x 24 cols = 1152 cp16 over 256 threads
        const float* wk = WTt_g + (size_t)k*(DR_*CA_) + (size_t)n0*CA_ + j*CHUNK;
        uint32_t bb = stb + (uint32_t)(STG_A_FL)*4u;
#pragma unroll
        for (int o = tid; o < 1152; o += NTHR) {
            int row = o / 6;
            int q   = o - row*6;
            cp16(bb + (uint32_t)(row*SROW + q*4)*4u, wk + (size_t)row*CA_ + q*4);
        }
    };

    // prologue: fill stages 0,1
    issue_copies(0); CP_COMMIT();
    issue_copies(1); CP_COMMIT();

    for (int t = 0; t < TCH; t++) {
        const int st = t & 3;
        const int k  = t >> 4;
        const int j  = t & 15;

        if (t + 2 < TCH) issue_copies(t + 2);
        CP_COMMIT();           // keep one group per iteration (may be empty)
        CP_WAIT2();            // chunk t landed (t+1, t+2 may be in flight)
        __syncthreads();

        if (j == 0) {
            // per-k pw table (consumed at j==15; barriers in between)
#pragma unroll
            for (int i = 0; i < 8; i++) {
                int e  = i*NTHR + tid;
                int m  = e & 127;
                int dl = e >> 7;
                const float* kp = KPO + (dl*K_ + k)*3;
                float w = MD[m*3+0]*kp[0] + MD[m*3+1]*kp[1] + MD[m*3+2]*kp[2];
                PW[m*17 + dl] = fmaxf(w, 0.f);
            }
        }

        const float* Ab = s + st*STG_FL;
        const float* Bb = Ab + STG_A_FL;
#pragma unroll
        for (int ks = 0; ks < NKS; ks++) {
            const int col = ks*8 + tig*2;
            uint32_t bbf[6][2];
#pragma unroll
            for (int nt = 0; nt < 6; nt++) {
                float2 v = *(const float2*)&Bb[(n0w + nt*8 + gid)*SROW + col];
                bbf[nt][0] = __float_as_uint(v.x);
                bbf[nt][1] = __float_as_uint(v.y);
            }
#pragma unroll
            for (int mt = 0; mt < 4; mt++) {
                int rb = m0w + mt*16 + gid;
                float2 alo = *(const float2*)&Ab[rb*SROW + col];
                float2 ahi = *(const float2*)&Ab[(rb+8)*SROW + col];
                uint32_t a0 = __float_as_uint(alo.x);
                uint32_t a1 = __float_as_uint(ahi.x);
                uint32_t a2 = __float_as_uint(alo.y);
                uint32_t a3 = __float_as_uint(ahi.y);
#pragma unroll
                for (int nt = 0; nt < 6; nt++)
                    mma_tf32(acc_k[mt][nt][0], acc_k[mt][nt][1], acc_k[mt][nt][2], acc_k[mt][nt][3],
                             a0, a1, a2, a3, bbf[nt][0], bbf[nt][1]);
            }
        }

        if (j == CPK-1) {
            // fold pw into register output accumulators
#pragma unroll
            for (int mt = 0; mt < 4; mt++) {
                int r0 = m0w + mt*16 + gid;
                int r1 = r0 + 8;
#pragma unroll
                for (int nt = 0; nt < 6; nt++) {
                    int dl = (n0w + nt*8 + tig*2) / 12;
                    float pw0 = PW[r0*17 + dl];
                    float pw1 = PW[r1*17 + dl];
                    acc_o[mt][nt][0] = fmaf(pw0, acc_k[mt][nt][0], acc_o[mt][nt][0]);
                    acc_o[mt][nt][1] = fmaf(pw0, acc_k[mt][nt][1], acc_o[mt][nt][1]);
                    acc_o[mt][nt][2] = fmaf(pw1, acc_k[mt][nt][2], acc_o[mt][nt][2]);
                    acc_o[mt][nt][3] = fmaf(pw1, acc_k[mt][nt][3], acc_o[mt][nt][3]);
                    acc_k[mt][nt][0] = 0.f; acc_k[mt][nt][1] = 0.f;
                    acc_k[mt][nt][2] = 0.f; acc_k[mt][nt][3] = 0.f;
                }
            }
        }
    }

    // ---- epilogue: bias + relu, direct global store (float2 per cell-row) ----
#pragma unroll
    for (int mt = 0; mt < 4; mt++) {
        int r0 = m0w + mt*16 + gid;
        int r1 = r0 + 8;
#pragma unroll
        for (int nt = 0; nt < 6; nt++) {
            int n  = n0w + nt*8 + tig*2;      // even -> pair stays within one d
            int d  = d0 + n / 12;
            int r  = n % 12;
            float be0 = BE[n], be1 = BE[n+1];
            float* o0 = out + ((size_t)(b*C2_ + d)*P_ + p0 + r0)*A_ + r;
            float* o1 = out + ((size_t)(b*C2_ + d)*P_ + p0 + r1)*A_ + r;
            *(float2*)o0 = make_float2(fmaxf(acc_o[mt][nt][0] + be0, 0.f),
                                       fmaxf(acc_o[mt][nt][1] + be1, 0.f));
            *(float2*)o1 = make_float2(fmaxf(acc_o[mt][nt][2] + be0, 0.f),
                                       fmaxf(acc_o[mt][nt][3] + be1, 0.f));
        }
    }
}

// ---------------------------------------------------------------------------
extern "C" void kernel_launch(void* const* d_in, const int* in_sizes, int n_in,
                              void* d_out, int out_size) {
    const int*   nbr     = (const int*)  d_in[0];
    const float* verts   = (const float*)d_in[1];
    const float* fm      = (const float*)d_in[2];
    const float* W       = (const float*)d_in[3];
    const float* bias    = (const float*)d_in[4];
    const float* kpw     = (const float*)d_in[5];
    const float* vs      = (const float*)d_in[6];
    const int*   idx_map = (const int*)  d_in[7];
    const int*   tivr    = (const int*)  d_in[8];
    const int*   tir     = (const int*)  d_in[9];
    const int*   lvl     = (const int*)  d_in[10];
    float* out = (float*)d_out;

    static int smem_set = 0;
    if (!smem_set) {
        cudaFuncSetAttribute(equi_mma, cudaFuncAttributeMaxDynamicSharedMemorySize, SMEM_BYTES);
        smem_set = 1;
    }

    build_wt<<<512, 256>>>(W, kpw, idx_map, tivr, tir);
    mean_dir_k<<<BP_/256, 256>>>(nbr, verts);
    prep_small<<<1, 512>>>(kpw, vs, idx_map, tivr, bias, lvl);

    dim3 grid(2, 128);
    equi_mma<<<grid, NTHR, SMEM_BYTES>>>(fm, out);
}

// round 8
// speedup vs baseline: 1.0651x; 1.0651x over previous
#include <cuda_runtime.h>
#include <cstdint>
#include <cstddef>

#define B_   2
#define P_   8192
#define NNB  24
#define C1_  32
#define C2_  32
#define K_   13
#define A_   12
#define DR_  (C2_*A_)   /* 384 */
#define CA_  (C1_*A_)   /* 384 */
#define BP_  (B_*P_)    /* 16384 */

#define CHUNK 24        /* K cols per stage (= 2 c-planes) */
#define CPK   16        /* chunks per k-segment (384/24) */
#define NKS   3         /* m16n8k8 steps per chunk */
#define TCH   (K_*CPK)  /* 208 chunks */
#define SROW  24        /* smem row stride: 96B, conflict-free (192g mod 32 = {0,24,16,8}) */
#define NSTG  3
#define NTHR  256

#define STG_A_FL  (128*SROW)            /* 3072 */
#define STG_FL    (STG_A_FL + 192*SROW) /* 7680 */

// ---- scratch (device globals; no allocation allowed) ----
__device__ float WTt_g[K_*DR_*CA_];  // [k][dr][ca], tf32-rounded (~7.7MB)
__device__ float md_g[BP_*3];
__device__ float kpo_g[C2_*K_*3];
__device__ float be_g[C2_*A_];

__device__ __forceinline__ uint32_t f2tf32(float x) {
    uint32_t u;
    asm("cvt.rna.tf32.f32 %0, %1;" : "=r"(u) : "f"(x));
    return u;
}
__device__ __forceinline__ uint32_t smem_u32(const void* p) {
    uint32_t a;
    asm("{ .reg .u64 t; cvta.to.shared.u64 t, %1; cvt.u32.u64 %0, t; }" : "=r"(a) : "l"(p));
    return a;
}
__device__ __forceinline__ void cp16(uint32_t dst, const void* src) {
    asm volatile("cp.async.cg.shared.global [%0], [%1], 16;" :: "r"(dst), "l"(src));
}
#define CP_COMMIT() asm volatile("cp.async.commit_group;" ::: "memory")
#define CP_WAIT1()  asm volatile("cp.async.wait_group 1;" ::: "memory")

__device__ __forceinline__ void mma_tf32(float& c0, float& c1, float& c2, float& c3,
                                         uint32_t a0, uint32_t a1, uint32_t a2, uint32_t a3,
                                         uint32_t b0, uint32_t b1) {
    asm volatile("mma.sync.aligned.m16n8k8.row.col.f32.tf32.tf32.f32 "
                 "{%0,%1,%2,%3}, {%4,%5,%6,%7}, {%8,%9}, {%0,%1,%2,%3};"
                 : "+f"(c0), "+f"(c1), "+f"(c2), "+f"(c3)
                 : "r"(a0), "r"(a1), "r"(a2), "r"(a3), "r"(b0), "r"(b1));
}

// ===================== prep kernels =====================
__global__ void build_wt(const float* __restrict__ W,
                         const float* __restrict__ kpw,
                         const int*   __restrict__ idx_map,
                         const int*   __restrict__ tivr,
                         const int*   __restrict__ tir) {
    int idx = blockIdx.x * blockDim.x + threadIdx.x;
    const int total = K_*DR_*CA_;
    for (; idx < total; idx += gridDim.x * blockDim.x) {
        int ca = idx % CA_;
        int t  = idx / CA_;
        int n  = t % DR_;
        int k  = t / DR_;
        int d = n / A_, r = n % A_;
        int c = ca / A_, a = ca % A_;
        int j = idx_map[tivr[r*K_ + k]*A_ + tir[r*A_ + a]];
        float v = W[(d*C1_ + c)*36 + j] * kpw[d*36 + j];
        ((uint32_t*)WTt_g)[idx] = f2tf32(v);
    }
}

__global__ void mean_dir_k(const int* __restrict__ nbr_idx,
                           const float* __restrict__ verts) {
    int bp = blockIdx.x * blockDim.x + threadIdx.x;
    if (bp >= BP_) return;
    int b = bp >> 13;
    int p = bp & (P_-1);
    const float* vb = verts + b * P_ * 3;
    float vx = vb[p*3+0], vy = vb[p*3+1], vz = vb[p*3+2];
    float sx = 0.f, sy = 0.f, sz = 0.f;
    const int* ni = nbr_idx + bp * NNB;
#pragma unroll 4
    for (int n = 0; n < NNB; n++) {
        int q = ni[n];
        float dx = vb[q*3+0] - vx;
        float dy = vb[q*3+1] - vy;
        float dz = vb[q*3+2] - vz;
        float nrm = sqrtf(dx*dx + dy*dy + dz*dz);
        float s = 1.0f / fmaxf(nrm, 1e-12f);
        sx += dx*s; sy += dy*s; sz += dz*s;
    }
    const float inv = 1.0f / (float)NNB;
    md_g[bp*3+0] = sx * inv;
    md_g[bp*3+1] = sy * inv;
    md_g[bp*3+2] = sz * inv;
}

__global__ void prep_small(const float* __restrict__ kpw,
                           const float* __restrict__ vs,
                           const int*   __restrict__ idx_map,
                           const int*   __restrict__ tivr,
                           const float* __restrict__ bias,
                           const int*   __restrict__ lvl) {
    int t = threadIdx.x;
    if (t < C2_*K_) {
        int d = t / K_, k = t % K_;
        float s0 = 0.f, s1 = 0.f, s2 = 0.f;
        for (int a = 0; a < A_; a++) {
            float w = kpw[d*36 + idx_map[k*A_ + a]];
            s0 += w * vs[a*3+0];
            s1 += w * vs[a*3+1];
            s2 += w * vs[a*3+2];
        }
        float nrm = sqrtf(s0*s0 + s1*s1 + s2*s2);
        float inv = 1.0f / fmaxf(nrm, 1e-12f);
        kpo_g[t*3+0] = s0*inv;
        kpo_g[t*3+1] = s1*inv;
        kpo_g[t*3+2] = s2*inv;
    }
    if (t < C2_*A_) {
        int d = t / A_, r = t % A_;
        float s = 0.f;
        for (int k = 0; k < K_; k++)
            s += bias[d*5 + lvl[tivr[r*K_ + k]]];
        be_g[t] = s;
    }
}

// ===================== main mma.sync tf32 kernel =====================
// 256 threads, warp grid 2m x 4n (warp tile 64x48), CTA tile 128x192.
// 3-stage cp.async ring, 1 syncthreads/chunk, acc_k in regs, per-k fold
// RMW'd straight into the (L2-resident) global out buffer. 2 CTAs/SM.
// smem (floats):
//   STAGES [3][7680] @0      (23040)
//   MD  [128][3]     @23040  (384)
//   KPO [16][13][3]  @23424  (624)
//   BE  [192]        @24048  (192)
#define OFF_MD  23040
#define OFF_KPO 23424
#define OFF_BE  24048
#define SMEM_FLOATS 24240
#define SMEM_BYTES (SMEM_FLOATS*4)   /* 96960 B -> 2 CTAs/SM */

__global__ __launch_bounds__(NTHR, 2) void equi_mma(const float* __restrict__ fm,
                                                    float* __restrict__ out) {
    extern __shared__ float s[];
    float* MD  = s + OFF_MD;
    float* KPO = s + OFF_KPO;
    float* BE  = s + OFF_BE;
    const uint32_t sS = smem_u32(s);

    const int tid  = threadIdx.x;
    const int wid  = tid >> 5;
    const int lane = tid & 31;
    const int gid  = lane >> 2;
    const int tig  = lane & 3;

    const int Ntile = blockIdx.x;        // 0..1
    const int Mtile = blockIdx.y;        // 0..127
    const int b  = Mtile >> 6;
    const int p0 = (Mtile & 63) << 7;
    const int n0 = Ntile * 192;
    const int d0 = Ntile * 16;

    // warp grid 2(m) x 4(n): warp tile 64m x 48n
    const int m0w = (wid & 1) * 64;
    const int n0w = (wid >> 1) * 48;

    for (int i = tid; i < 128*3; i += NTHR) MD[i]  = md_g[(size_t)Mtile*128*3 + i];
    for (int i = tid; i < 16*K_*3; i += NTHR) KPO[i] = kpo_g[d0*(K_*3) + i];
    if (tid < 192) BE[tid] = be_g[d0*A_ + tid];

    const float* fmb = fm + (size_t)b * C1_ * K_ * P_ * A_;

    float acc_k[4][6][4];
#pragma unroll
    for (int mt = 0; mt < 4; mt++)
#pragma unroll
        for (int nt = 0; nt < 6; nt++)
#pragma unroll
            for (int q = 0; q < 4; q++) acc_k[mt][nt][q] = 0.f;

    const int rowA = tid & 127;
    const int csA  = tid >> 7;

    auto issue_copies = [&](int t) {
        int k  = t >> 4;
        int j  = t & 15;
        int st = t % NSTG;
        uint32_t stb = sS + (uint32_t)(st*STG_FL)*4u;
        // A: 128 rows x 24 cols (2 c-planes), 3 cp16 per thread
        {
            int c = j*2 + csA;
            const float* src = fmb + ((size_t)(c*K_ + k)*P_ + p0 + rowA)*A_;
            uint32_t dst = stb + (uint32_t)(rowA*SROW + csA*12)*4u;
#pragma unroll
            for (int q = 0; q < 3; q++)
                cp16(dst + q*16u, src + q*4);
        }
        // B: 192 rows x 24 cols = 1152 cp16 over 256 threads
        const float* wk = WTt_g + (size_t)k*(DR_*CA_) + (size_t)n0*CA_ + j*CHUNK;
        uint32_t bb = stb + (uint32_t)(STG_A_FL)*4u;
#pragma unroll
        for (int o = tid; o < 1152; o += NTHR) {
            int row = o / 6;
            int q   = o - row*6;
            cp16(bb + (uint32_t)(row*SROW + q*4)*4u, wk + (size_t)row*CA_ + q*4);
        }
    };

    // prologue: stages 0,1
    issue_copies(0); CP_COMMIT();
    issue_copies(1); CP_COMMIT();
    __syncthreads();           // small tables visible

    for (int t = 0; t < TCH; t++) {
        const int st = t % NSTG;
        const int k  = t >> 4;
        const int j  = t & 15;

        CP_WAIT1();            // group t done (t+1 may fly)
        __syncthreads();       // visibility + stage (t-1)%3 free

        const float* Ab = s + st*STG_FL;
        const float* Bb = Ab + STG_A_FL;
#pragma unroll
        for (int ks = 0; ks < NKS; ks++) {
            const int col = ks*8 + tig*2;
            uint32_t bbf[6][2];
#pragma unroll
            for (int nt = 0; nt < 6; nt++) {
                float2 v = *(const float2*)&Bb[(n0w + nt*8 + gid)*SROW + col];
                bbf[nt][0] = __float_as_uint(v.x);
                bbf[nt][1] = __float_as_uint(v.y);
            }
#pragma unroll
            for (int mt = 0; mt < 4; mt++) {
                int rb = m0w + mt*16 + gid;
                float2 alo = *(const float2*)&Ab[rb*SROW + col];
                float2 ahi = *(const float2*)&Ab[(rb+8)*SROW + col];
                uint32_t a0 = __float_as_uint(alo.x);
                uint32_t a1 = __float_as_uint(ahi.x);
                uint32_t a2 = __float_as_uint(alo.y);
                uint32_t a3 = __float_as_uint(ahi.y);
#pragma unroll
                for (int nt = 0; nt < 6; nt++)
                    mma_tf32(acc_k[mt][nt][0], acc_k[mt][nt][1], acc_k[mt][nt][2], acc_k[mt][nt][3],
                             a0, a1, a2, a3, bbf[nt][0], bbf[nt][1]);
            }
        }

        if (j == CPK-1) {
            // fold: out(+)= pw * acc_k   (CTA-disjoint region; L2-resident)
#pragma unroll
            for (int mt = 0; mt < 4; mt++) {
                int r0 = m0w + mt*16 + gid;
                int r1 = r0 + 8;
                float m0x = MD[r0*3+0], m0y = MD[r0*3+1], m0z = MD[r0*3+2];
                float m1x = MD[r1*3+0], m1y = MD[r1*3+1], m1z = MD[r1*3+2];
#pragma unroll
                for (int nt = 0; nt < 6; nt++) {
                    int n  = n0w + nt*8 + tig*2;
                    int dl = n / 12;
                    int rr = n % 12;
                    const float* kp = KPO + (dl*K_ + k)*3;
                    float pw0 = fmaxf(m0x*kp[0] + m0y*kp[1] + m0z*kp[2], 0.f);
                    float pw1 = fmaxf(m1x*kp[0] + m1y*kp[1] + m1z*kp[2], 0.f);
                    float* o0 = out + ((size_t)(b*C2_ + d0 + dl)*P_ + p0 + r0)*A_ + rr;
                    float* o1 = out + ((size_t)(b*C2_ + d0 + dl)*P_ + p0 + r1)*A_ + rr;
                    if (k == 0) {
                        *(float2*)o0 = make_float2(pw0*acc_k[mt][nt][0], pw0*acc_k[mt][nt][1]);
                        *(float2*)o1 = make_float2(pw1*acc_k[mt][nt][2], pw1*acc_k[mt][nt][3]);
                    } else if (k == K_-1) {
                        float2 c0 = *(float2*)o0, c1 = *(float2*)o1;
                        float be0 = BE[n], be1 = BE[n+1];
                        c0.x = fmaxf(fmaf(pw0, acc_k[mt][nt][0], c0.x) + be0, 0.f);
                        c0.y = fmaxf(fmaf(pw0, acc_k[mt][nt][1], c0.y) + be1, 0.f);
                        c1.x = fmaxf(fmaf(pw1, acc_k[mt][nt][2], c1.x) + be0, 0.f);
                        c1.y = fmaxf(fmaf(pw1, acc_k[mt][nt][3], c1.y) + be1, 0.f);
                        *(float2*)o0 = c0;
                        *(float2*)o1 = c1;
                    } else {
                        float2 c0 = *(float2*)o0, c1 = *(float2*)o1;
                        c0.x = fmaf(pw0, acc_k[mt][nt][0], c0.x);
                        c0.y = fmaf(pw0, acc_k[mt][nt][1], c0.y);
                        c1.x = fmaf(pw1, acc_k[mt][nt][2], c1.x);
                        c1.y = fmaf(pw1, acc_k[mt][nt][3], c1.y);
                        *(float2*)o0 = c0;
                        *(float2*)o1 = c1;
                    }
                    acc_k[mt][nt][0] = 0.f; acc_k[mt][nt][1] = 0.f;
                    acc_k[mt][nt][2] = 0.f; acc_k[mt][nt][3] = 0.f;
                }
            }
        }

        // issue copies for t+2 into stage (t+2)%3 == (t-1)%3 (freed above)
        if (t + 2 < TCH) issue_copies(t + 2);
        CP_COMMIT();           // one group per iteration (possibly empty)
    }
}

// ---------------------------------------------------------------------------
extern "C" void kernel_launch(void* const* d_in, const int* in_sizes, int n_in,
                              void* d_out, int out_size) {
    const int*   nbr     = (const int*)  d_in[0];
    const float* verts   = (const float*)d_in[1];
    const float* fm      = (const float*)d_in[2];
    const float* W       = (const float*)d_in[3];
    const float* bias    = (const float*)d_in[4];
    const float* kpw     = (const float*)d_in[5];
    const float* vs      = (const float*)d_in[6];
    const int*   idx_map = (const int*)  d_in[7];
    const int*   tivr    = (const int*)  d_in[8];
    const int*   tir     = (const int*)  d_in[9];
    const int*   lvl     = (const int*)  d_in[10];
    float* out = (float*)d_out;

    static int smem_set = 0;
    if (!smem_set) {
        cudaFuncSetAttribute(equi_mma, cudaFuncAttributeMaxDynamicSharedMemorySize, SMEM_BYTES);
        smem_set = 1;
    }

    build_wt<<<512, 256>>>(W, kpw, idx_map, tivr, tir);
    mean_dir_k<<<BP_/256, 256>>>(nbr, verts);
    prep_small<<<1, 512>>>(kpw, vs, idx_map, tivr, bias, lvl);

    dim3 grid(2, 128);
    equi_mma<<<grid, NTHR, SMEM_BYTES>>>(fm, out);
}

// round 9
// speedup vs baseline: 1.5930x; 1.4957x over previous
#include <cuda_runtime.h>
#include <cuda_bf16.h>
#include <cstdint>
#include <cstddef>

#define B_   2
#define P_   8192
#define NNB  24
#define C1_  32
#define C2_  32
#define K_   13
#define A_   12
#define DR_  (C2_*A_)   /* 384 */
#define CA_  (C1_*A_)   /* 384 */
#define BP_  (B_*P_)    /* 16384 */

#define CHUNK 48        /* K cols per stage (4 c-planes) */
#define CPK   8         /* chunks per k-segment (384/48) */
#define NKB   3         /* m16n8k16 steps per chunk */
#define TCH   (K_*CPK)  /* 104 chunks */
#define NSTG  3
#define NTHR  256

#define STG_A_BY  (128*96)              /* 12288 B */
#define STG_BY    (STG_A_BY + 192*96)   /* 30720 B */

// ---- scratch (device globals; no allocation allowed) ----
__device__ __nv_bfloat16 fmbf_g[(size_t)B_*K_*CPK*P_*CHUNK];  // [b][k][j][p][48] (~164MB)
__device__ __nv_bfloat16 WTb_g[K_*DR_*CA_];                   // [k][dr][ca] bf16 (~3.8MB)
__device__ float md_g[BP_*3];
__device__ float kpo_g[C2_*K_*3];
__device__ float be_g[C2_*A_];

__device__ __forceinline__ uint32_t smem_u32(const void* p) {
    uint32_t a;
    asm("{ .reg .u64 t; cvta.to.shared.u64 t, %1; cvt.u32.u64 %0, t; }" : "=r"(a) : "l"(p));
    return a;
}
__device__ __forceinline__ void cp16(uint32_t dst, const void* src) {
    asm volatile("cp.async.cg.shared.global [%0], [%1], 16;" :: "r"(dst), "l"(src));
}
#define CP_COMMIT() asm volatile("cp.async.commit_group;" ::: "memory")
#define CP_WAIT1()  asm volatile("cp.async.wait_group 1;" ::: "memory")

__device__ __forceinline__ void mma_bf16(float& c0, float& c1, float& c2, float& c3,
                                         uint32_t a0, uint32_t a1, uint32_t a2, uint32_t a3,
                                         uint32_t b0, uint32_t b1) {
    asm volatile("mma.sync.aligned.m16n8k16.row.col.f32.bf16.bf16.f32 "
                 "{%0,%1,%2,%3}, {%4,%5,%6,%7}, {%8,%9}, {%0,%1,%2,%3};"
                 : "+f"(c0), "+f"(c1), "+f"(c2), "+f"(c3)
                 : "r"(a0), "r"(a1), "r"(a2), "r"(a3), "r"(b0), "r"(b1));
}

// ===================== prep kernels =====================
// B: WTb[k][n][ca] = bf16( W[d,c,j]*kpw[d,j] ), two cols per thread (packed store)
__global__ void build_wt(const float* __restrict__ W,
                         const float* __restrict__ kpw,
                         const int*   __restrict__ idx_map,
                         const int*   __restrict__ tivr,
                         const int*   __restrict__ tir) {
    int u = blockIdx.x * blockDim.x + threadIdx.x;
    const int total2 = K_*DR_*CA_/2;
    for (; u < total2; u += gridDim.x * blockDim.x) {
        int idx = u*2;
        int ca = idx % CA_;
        int t  = idx / CA_;
        int n  = t % DR_;
        int k  = t / DR_;
        int d = n / A_, r = n % A_;
        __nv_bfloat162 h;
        {
            int c = ca / A_, a = ca % A_;
            int j = idx_map[tivr[r*K_ + k]*A_ + tir[r*A_ + a]];
            h.x = __float2bfloat16_rn(W[(d*C1_ + c)*36 + j] * kpw[d*36 + j]);
        }
        {
            int ca2 = ca + 1;
            int c = ca2 / A_, a = ca2 % A_;
            int j = idx_map[tivr[r*K_ + k]*A_ + tir[r*A_ + a]];
            h.y = __float2bfloat16_rn(W[(d*C1_ + c)*36 + j] * kpw[d*36 + j]);
        }
        *(__nv_bfloat162*)(WTb_g + idx) = h;
    }
}

// A: fmbf[b][k][j][p][48] = bf16(fm[b][c=j*4+pc/12][k][p][pc%12]), one 16B out/thread
#define TOT16 ((size_t)B_*K_*CPK*P_*6)
__global__ void conv_fm(const float* __restrict__ fm) {
    size_t o = (size_t)blockIdx.x * blockDim.x + threadIdx.x;
    if (o >= TOT16) return;
    int    q    = (int)(o % 6);
    size_t rest = o / 6;
    int    p    = (int)(rest & (P_-1));
    size_t r2   = rest >> 13;
    int    j    = (int)(r2 & (CPK-1));
    size_t bk   = r2 >> 3;
    int    k    = (int)(bk % K_);
    int    b    = (int)(bk / K_);
    const float* f0 = fm + (size_t)b * C1_ * K_ * P_ * A_;
    int pc0 = q*8;
    uint32_t w[4];
#pragma unroll
    for (int e = 0; e < 4; e++) {
        int pA = pc0 + e*2, pB = pA + 1;
        int cA = j*4 + pA/12, aA = pA - (pA/12)*12;
        int cB = j*4 + pB/12, aB = pB - (pB/12)*12;
        float xA = f0[((size_t)(cA*K_ + k)*P_ + p)*A_ + aA];
        float xB = f0[((size_t)(cB*K_ + k)*P_ + p)*A_ + aB];
        __nv_bfloat162 h;
        h.x = __float2bfloat16_rn(xA);
        h.y = __float2bfloat16_rn(xB);
        w[e] = *(uint32_t*)&h;
    }
    ((uint4*)fmbf_g)[o] = make_uint4(w[0], w[1], w[2], w[3]);
}

__global__ void mean_dir_k(const int* __restrict__ nbr_idx,
                           const float* __restrict__ verts) {
    int bp = blockIdx.x * blockDim.x + threadIdx.x;
    if (bp >= BP_) return;
    int b = bp >> 13;
    int p = bp & (P_-1);
    const float* vb = verts + b * P_ * 3;
    float vx = vb[p*3+0], vy = vb[p*3+1], vz = vb[p*3+2];
    float sx = 0.f, sy = 0.f, sz = 0.f;
    const int* ni = nbr_idx + bp * NNB;
#pragma unroll 4
    for (int n = 0; n < NNB; n++) {
        int q = ni[n];
        float dx = vb[q*3+0] - vx;
        float dy = vb[q*3+1] - vy;
        float dz = vb[q*3+2] - vz;
        float nrm = sqrtf(dx*dx + dy*dy + dz*dz);
        float s = 1.0f / fmaxf(nrm, 1e-12f);
        sx += dx*s; sy += dy*s; sz += dz*s;
    }
    const float inv = 1.0f / (float)NNB;
    md_g[bp*3+0] = sx * inv;
    md_g[bp*3+1] = sy * inv;
    md_g[bp*3+2] = sz * inv;
}

__global__ void prep_small(const float* __restrict__ kpw,
                           const float* __restrict__ vs,
                           const int*   __restrict__ idx_map,
                           const int*   __restrict__ tivr,
                           const float* __restrict__ bias,
                           const int*   __restrict__ lvl) {
    int t = threadIdx.x;
    if (t < C2_*K_) {
        int d = t / K_, k = t % K_;
        float s0 = 0.f, s1 = 0.f, s2 = 0.f;
        for (int a = 0; a < A_; a++) {
            float w = kpw[d*36 + idx_map[k*A_ + a]];
            s0 += w * vs[a*3+0];
            s1 += w * vs[a*3+1];
            s2 += w * vs[a*3+2];
        }
        float nrm = sqrtf(s0*s0 + s1*s1 + s2*s2);
        float inv = 1.0f / fmaxf(nrm, 1e-12f);
        kpo_g[t*3+0] = s0*inv;
        kpo_g[t*3+1] = s1*inv;
        kpo_g[t*3+2] = s2*inv;
    }
    if (t < C2_*A_) {
        int d = t / A_, r = t % A_;
        float s = 0.f;
        for (int k = 0; k < K_; k++)
            s += bias[d*5 + lvl[tivr[r*K_ + k]]];
        be_g[t] = s;
    }
}

// ===================== main bf16 mma kernel =====================
// 256 threads, warp grid 2m x 4n (warp tile 64x48), CTA tile 128x192.
// 3-stage cp.async ring, 1 sync/chunk, acc in regs, per-k fold -> global out.
// smem: stages [3][30720 B] @0 (=23040 floats), then MD/KPO/BE (same as R8).
#define OFF_MD  23040
#define OFF_KPO 23424
#define OFF_BE  24048
#define SMEM_FLOATS 24240
#define SMEM_BYTES (SMEM_FLOATS*4)   /* 96960 B -> 2 CTAs/SM */

__global__ __launch_bounds__(NTHR, 2) void equi_mma(float* __restrict__ out) {
    extern __shared__ float s[];
    char*  sc  = (char*)s;
    float* MD  = s + OFF_MD;
    float* KPO = s + OFF_KPO;
    float* BE  = s + OFF_BE;
    const uint32_t sS = smem_u32(s);

    const int tid  = threadIdx.x;
    const int wid  = tid >> 5;
    const int lane = tid & 31;
    const int gid  = lane >> 2;
    const int tig  = lane & 3;

    const int Ntile = blockIdx.x;        // 0..1
    const int Mtile = blockIdx.y;        // 0..127
    const int b  = Mtile >> 6;
    const int p0 = (Mtile & 63) << 7;
    const int n0 = Ntile * 192;
    const int d0 = Ntile * 16;

    const int m0w = (wid & 1) * 64;      // warp tile 64m x 48n
    const int n0w = (wid >> 1) * 48;

    for (int i = tid; i < 128*3; i += NTHR) MD[i]  = md_g[(size_t)Mtile*128*3 + i];
    for (int i = tid; i < 16*K_*3; i += NTHR) KPO[i] = kpo_g[d0*(K_*3) + i];
    if (tid < 192) BE[tid] = be_g[d0*A_ + tid];

    float acc_k[4][6][4];
#pragma unroll
    for (int mt = 0; mt < 4; mt++)
#pragma unroll
        for (int nt = 0; nt < 6; nt++)
#pragma unroll
            for (int q = 0; q < 4; q++) acc_k[mt][nt][q] = 0.f;

    // per-thread copy offsets (constant across chunks)
    // A: linear 12288 B tile -> 3 x cp16 at tid*16 + i*4096
    // B: 192 rows x 96 B; o = tid + i*256 -> row = o/6, q = o%6
    uint32_t offBg[5], offBs[5];
#pragma unroll
    for (int i = 0; i < 5; i++) {
        int o   = tid + i*NTHR;
        int row = o / 6;
        int q   = o - row*6;
        offBg[i] = (uint32_t)(row*768 + q*16);   // global: WTb row stride 768 B
        offBs[i] = (uint32_t)(row*96  + q*16);   // smem:   96 B rows
    }
    const char* fm_base  = (const char*)fmbf_g + (size_t)b*(K_*CPK*P_*96);
    const char* wtb_base = (const char*)WTb_g + (size_t)n0*768;

    auto issue_copies = [&](int t) {
        int k  = t >> 3;
        int j  = t & 7;
        int st = t;  st -= (st >= NSTG ? NSTG*(st/NSTG) : 0);   // t % 3
        uint32_t dstA = sS + (uint32_t)(t % NSTG)*STG_BY;
        const char* asrc = fm_base + ((size_t)(k*CPK + j)*P_ + p0)*96;
#pragma unroll
        for (int i = 0; i < 3; i++)
            cp16(dstA + (uint32_t)(tid*16 + i*4096), asrc + tid*16 + i*4096);
        const char* bsrc = wtb_base + (size_t)k*(DR_*CA_*2) + j*96;
        uint32_t dstB = dstA + STG_A_BY;
#pragma unroll
        for (int i = 0; i < 4; i++)
            cp16(dstB + offBs[i], bsrc + offBg[i]);
        if (tid < 128)
            cp16(dstB + offBs[4], bsrc + offBg[4]);
    };

    // prologue: stages 0,1
    issue_copies(0); CP_COMMIT();
    issue_copies(1); CP_COMMIT();
    __syncthreads();           // small tables visible

    for (int t = 0; t < TCH; t++) {
        const int st = t % NSTG;
        const int k  = t >> 3;
        const int j  = t & 7;

        CP_WAIT1();            // group t landed (t+1 may fly)
        __syncthreads();

        const char* Ab = sc + st*STG_BY;
        const char* Bb = Ab + STG_A_BY;
#pragma unroll
        for (int kb = 0; kb < NKB; kb++) {
            const int co = kb*32 + tig*8;
            uint32_t bf[6][2];
#pragma unroll
            for (int nt = 0; nt < 6; nt++) {
                uint2 v = *(const uint2*)(Bb + (n0w + nt*8 + gid)*96 + co);
                bf[nt][0] = v.x; bf[nt][1] = v.y;
            }
#pragma unroll
            for (int mt = 0; mt < 4; mt++) {
                int rb = m0w + mt*16 + gid;
                uint2 lo = *(const uint2*)(Ab + rb*96 + co);        // a0,a2
                uint2 hi = *(const uint2*)(Ab + (rb+8)*96 + co);    // a1,a3
#pragma unroll
                for (int nt = 0; nt < 6; nt++)
                    mma_bf16(acc_k[mt][nt][0], acc_k[mt][nt][1], acc_k[mt][nt][2], acc_k[mt][nt][3],
                             lo.x, hi.x, lo.y, hi.y, bf[nt][0], bf[nt][1]);
            }
        }

        if (j == CPK-1) {
            // fold: out (+)= pw * acc_k  (CTA-disjoint; L2-resident)
#pragma unroll
            for (int mt = 0; mt < 4; mt++) {
                int r0 = m0w + mt*16 + gid;
                int r1 = r0 + 8;
                float m0x = MD[r0*3+0], m0y = MD[r0*3+1], m0z = MD[r0*3+2];
                float m1x = MD[r1*3+0], m1y = MD[r1*3+1], m1z = MD[r1*3+2];
#pragma unroll
                for (int nt = 0; nt < 6; nt++) {
                    int n  = n0w + nt*8 + tig*2;
                    int dl = n / 12;
                    int rr = n % 12;
                    const float* kp = KPO + (dl*K_ + k)*3;
                    float pw0 = fmaxf(m0x*kp[0] + m0y*kp[1] + m0z*kp[2], 0.f);
                    float pw1 = fmaxf(m1x*kp[0] + m1y*kp[1] + m1z*kp[2], 0.f);
                    float* o0 = out + ((size_t)(b*C2_ + d0 + dl)*P_ + p0 + r0)*A_ + rr;
                    float* o1 = out + ((size_t)(b*C2_ + d0 + dl)*P_ + p0 + r1)*A_ + rr;
                    if (k == 0) {
                        *(float2*)o0 = make_float2(pw0*acc_k[mt][nt][0], pw0*acc_k[mt][nt][1]);
                        *(float2*)o1 = make_float2(pw1*acc_k[mt][nt][2], pw1*acc_k[mt][nt][3]);
                    } else if (k == K_-1) {
                        float2 c0 = *(float2*)o0, c1 = *(float2*)o1;
                        float be0 = BE[n], be1 = BE[n+1];
                        c0.x = fmaxf(fmaf(pw0, acc_k[mt][nt][0], c0.x) + be0, 0.f);
                        c0.y = fmaxf(fmaf(pw0, acc_k[mt][nt][1], c0.y) + be1, 0.f);
                        c1.x = fmaxf(fmaf(pw1, acc_k[mt][nt][2], c1.x) + be0, 0.f);
                        c1.y = fmaxf(fmaf(pw1, acc_k[mt][nt][3], c1.y) + be1, 0.f);
                        *(float2*)o0 = c0;
                        *(float2*)o1 = c1;
                    } else {
                        float2 c0 = *(float2*)o0, c1 = *(float2*)o1;
                        c0.x = fmaf(pw0, acc_k[mt][nt][0], c0.x);
                        c0.y = fmaf(pw0, acc_k[mt][nt][1], c0.y);
                        c1.x = fmaf(pw1, acc_k[mt][nt][2], c1.x);
                        c1.y = fmaf(pw1, acc_k[mt][nt][3], c1.y);
                        *(float2*)o0 = c0;
                        *(float2*)o1 = c1;
                    }
                    acc_k[mt][nt][0] = 0.f; acc_k[mt][nt][1] = 0.f;
                    acc_k[mt][nt][2] = 0.f; acc_k[mt][nt][3] = 0.f;
                }
            }
        }

        if (t + 2 < TCH) issue_copies(t + 2);   // stage (t+2)%3 == (t-1)%3, freed
        CP_COMMIT();
    }
}

// ---------------------------------------------------------------------------
extern "C" void kernel_launch(void* const* d_in, const int* in_sizes, int n_in,
                              void* d_out, int out_size) {
    const int*   nbr     = (const int*)  d_in[0];
    const float* verts   = (const float*)d_in[1];
    const float* fm      = (const float*)d_in[2];
    const float* W       = (const float*)d_in[3];
    const float* bias    = (const float*)d_in[4];
    const float* kpw     = (const float*)d_in[5];
    const float* vs      = (const float*)d_in[6];
    const int*   idx_map = (const int*)  d_in[7];
    const int*   tivr    = (const int*)  d_in[8];
    const int*   tir     = (const int*)  d_in[9];
    const int*   lvl     = (const int*)  d_in[10];
    float* out = (float*)d_out;

    static int smem_set = 0;
    if (!smem_set) {
        cudaFuncSetAttribute(equi_mma, cudaFuncAttributeMaxDynamicSharedMemorySize, SMEM_BYTES);
        smem_set = 1;
    }

    build_wt<<<256, 256>>>(W, kpw, idx_map, tivr, tir);
    conv_fm<<<(int)((TOT16 + 255)/256), 256>>>(fm);
    mean_dir_k<<<BP_/256, 256>>>(nbr, verts);
    prep_small<<<1, 512>>>(kpw, vs, idx_map, tivr, bias, lvl);

    dim3 grid(2, 128);
    equi_mma<<<grid, NTHR, SMEM_BYTES>>>(out);
}